// round 1
// baseline (speedup 1.0000x reference)
#include <cuda_runtime.h>

#define M_KW 512          // B*N keywords
#define K_D  768          // d_model
#define T_DIM 512         // CLIP text dim
#define V_SZ 49408        // vocab
#define EPSF 1e-8f

// ---------------- scratch (device globals: no allocation allowed) -------------
__device__ float g_kw[M_KW * T_DIM];                 // projected keywords [512,512]
__device__ float g_invn[V_SZ];                       // 1/max(||emb_v||, eps)
__device__ unsigned long long g_best[M_KW];          // packed (key<<32 | ~v)

// ---------------- helpers ------------------------------------------------------
__device__ __forceinline__ unsigned fkey(float s) {
    unsigned u = __float_as_uint(s);
    return (u & 0x80000000u) ? ~u : (u | 0x80000000u);   // order-preserving map
}

__global__ void k_init() {
    int i = blockIdx.x * blockDim.x + threadIdx.x;
    if (i < M_KW) g_best[i] = 0ull;   // below key of any finite float
}

// ---------------- K1: kw = audio @ W + b  (512x768 @ 768x512) ------------------
__global__ __launch_bounds__(256) void k_proj(const float* __restrict__ A,
                                              const float* __restrict__ W,
                                              const float* __restrict__ b) {
    const int BM = 64, BN = 64, BK = 16;
    __shared__ float As[BK][BM + 4];
    __shared__ float Ws[BK][BN];
    int tid = threadIdx.x;
    int tx = tid & 15, ty = tid >> 4;
    int n0 = blockIdx.x * BN, m0 = blockIdx.y * BM;
    float acc[4][4] = {};
    for (int k0 = 0; k0 < K_D; k0 += BK) {
        #pragma unroll
        for (int i = 0; i < 4; ++i) {
            int idx = tid + i * 256;
            int r = idx >> 4, kk = idx & 15;
            As[kk][r] = A[(m0 + r) * K_D + k0 + kk];
        }
        #pragma unroll
        for (int i = 0; i < 4; ++i) {
            int idx = tid + i * 256;
            int kk = idx >> 6, n = idx & 63;
            Ws[kk][n] = W[(k0 + kk) * T_DIM + n0 + n];
        }
        __syncthreads();
        #pragma unroll
        for (int kk = 0; kk < BK; ++kk) {
            float av[4], bv[4];
            #pragma unroll
            for (int i = 0; i < 4; ++i) av[i] = As[kk][ty * 4 + i];
            #pragma unroll
            for (int j = 0; j < 4; ++j) bv[j] = Ws[kk][tx * 4 + j];
            #pragma unroll
            for (int i = 0; i < 4; ++i)
                #pragma unroll
                for (int j = 0; j < 4; ++j)
                    acc[i][j] = fmaf(av[i], bv[j], acc[i][j]);
        }
        __syncthreads();
    }
    #pragma unroll
    for (int i = 0; i < 4; ++i)
        #pragma unroll
        for (int j = 0; j < 4; ++j)
            g_kw[(m0 + ty * 4 + i) * T_DIM + n0 + tx * 4 + j] =
                acc[i][j] + b[n0 + tx * 4 + j];
}

// ---------------- K2: emb row inverse norms ------------------------------------
__global__ void k_norms(const float* __restrict__ emb) {
    int row = blockIdx.x * 8 + (threadIdx.x >> 5);
    int lane = threadIdx.x & 31;
    const float4* p = (const float4*)(emb + (size_t)row * T_DIM);
    float ss = 0.f;
    #pragma unroll
    for (int i = 0; i < 4; ++i) {
        float4 v = p[lane + i * 32];
        ss += v.x * v.x + v.y * v.y + v.z * v.z + v.w * v.w;
    }
    #pragma unroll
    for (int o = 16; o; o >>= 1) ss += __shfl_xor_sync(0xffffffffu, ss, o);
    if (lane == 0) g_invn[row] = 1.0f / fmaxf(sqrtf(ss), EPSF);
}

// ---------------- K3: scores + fused argmax ------------------------------------
// C[m][v] = (kw[m,:] . emb[v,:]) * invn[v]; per-m argmax over v, packed atomicMax.
// BM=BN=128, BK=16, 256 threads, 8x8 microtile, double-buffered smem.
__device__ __forceinline__ void st4(float* base, int stride, int k0, int m, float4 v) {
    base[(k0 + 0) * stride + m] = v.x;
    base[(k0 + 1) * stride + m] = v.y;
    base[(k0 + 2) * stride + m] = v.z;
    base[(k0 + 3) * stride + m] = v.w;
}

__global__ __launch_bounds__(256, 2) void k_score(const float* __restrict__ emb) {
    const int BM = 128, BN = 128, BK = 16;
    const int LDA = BM + 4;                       // 132 floats: keeps float4 align
    __shared__ __align__(16) float smf[2 * BK * LDA * 2];   // A then B, 33792 B
    float* Asf = smf;                              // [2][BK][LDA]
    float* Bsf = smf + 2 * BK * LDA;               // [2][BK][LDA]

    int tid = threadIdx.x;
    int tx = tid & 15, ty = tid >> 4;
    int m0 = blockIdx.x * BM;                      // gridDim.x = 4  (same-n adjacent)
    int n0 = blockIdx.y * BN;                      // gridDim.y = 386

    int rowL = tid >> 2;
    int kq4 = (tid & 3) * 4;

    // prologue: stage 0
    {
        float4 a0 = *(const float4*)&g_kw[(m0 + rowL) * T_DIM + kq4];
        float4 a1 = *(const float4*)&g_kw[(m0 + rowL + 64) * T_DIM + kq4];
        float4 b0 = *(const float4*)&emb[(size_t)(n0 + rowL) * T_DIM + kq4];
        float4 b1 = *(const float4*)&emb[(size_t)(n0 + rowL + 64) * T_DIM + kq4];
        st4(Asf, LDA, kq4, rowL, a0);
        st4(Asf, LDA, kq4, rowL + 64, a1);
        st4(Bsf, LDA, kq4, rowL, b0);
        st4(Bsf, LDA, kq4, rowL + 64, b1);
    }
    __syncthreads();

    float acc[8][8] = {};
    const int NT = T_DIM / BK;                     // 32
    for (int kt = 0; kt < NT; ++kt) {
        int buf = kt & 1;
        float4 a0, a1, b0, b1;
        bool pf = (kt + 1 < NT);
        if (pf) {
            int k0 = (kt + 1) * BK + kq4;
            a0 = *(const float4*)&g_kw[(m0 + rowL) * T_DIM + k0];
            a1 = *(const float4*)&g_kw[(m0 + rowL + 64) * T_DIM + k0];
            b0 = *(const float4*)&emb[(size_t)(n0 + rowL) * T_DIM + k0];
            b1 = *(const float4*)&emb[(size_t)(n0 + rowL + 64) * T_DIM + k0];
        }
        float* Ab = Asf + buf * BK * LDA;
        float* Bb = Bsf + buf * BK * LDA;
        #pragma unroll
        for (int k = 0; k < BK; ++k) {
            float a[8], bb[8];
            *(float4*)&a[0]  = *(const float4*)&Ab[k * LDA + ty * 8];
            *(float4*)&a[4]  = *(const float4*)&Ab[k * LDA + ty * 8 + 4];
            *(float4*)&bb[0] = *(const float4*)&Bb[k * LDA + tx * 8];
            *(float4*)&bb[4] = *(const float4*)&Bb[k * LDA + tx * 8 + 4];
            #pragma unroll
            for (int i = 0; i < 8; ++i)
                #pragma unroll
                for (int j = 0; j < 8; ++j)
                    acc[i][j] = fmaf(a[i], bb[j], acc[i][j]);
        }
        if (pf) {
            int nb = buf ^ 1;
            st4(Asf + nb * BK * LDA, LDA, kq4, rowL, a0);
            st4(Asf + nb * BK * LDA, LDA, kq4, rowL + 64, a1);
            st4(Bsf + nb * BK * LDA, LDA, kq4, rowL, b0);
            st4(Bsf + nb * BK * LDA, LDA, kq4, rowL + 64, b1);
        }
        __syncthreads();
    }

    // epilogue: scale by inv norm, per-row argmax, two-level reduce
    float inv[8];
    *(float4*)&inv[0] = *(const float4*)&g_invn[n0 + tx * 8];
    *(float4*)&inv[4] = *(const float4*)&g_invn[n0 + tx * 8 + 4];

    unsigned long long* red = (unsigned long long*)smf;   // [128][17] = 17408 B, fits
    #pragma unroll
    for (int i = 0; i < 8; ++i) {
        float bs = -3.0e38f; int bj = 0;
        #pragma unroll
        for (int j = 0; j < 8; ++j) {
            float s = acc[i][j] * inv[j];
            if (s > bs) { bs = s; bj = j; }       // strict > : first index on ties
        }
        unsigned v = (unsigned)(n0 + tx * 8 + bj);
        unsigned long long pk =
            ((unsigned long long)fkey(bs) << 32) | (0xFFFFFFFFu - v);  // ties -> smaller v
        red[(ty * 8 + i) * 17 + tx] = pk;
    }
    __syncthreads();
    if (tid < 128) {
        unsigned long long best = red[tid * 17];
        #pragma unroll
        for (int c = 1; c < 16; ++c) {
            unsigned long long x = red[tid * 17 + c];
            best = (x > best) ? x : best;
        }
        atomicMax(&g_best[m0 + tid], best);
    }
}

// ---------------- K4: gather selected embeddings --------------------------------
__global__ void k_gather(const float* __restrict__ emb, float* __restrict__ out) {
    int m = blockIdx.x;
    unsigned v = 0xFFFFFFFFu - (unsigned)(g_best[m] & 0xFFFFFFFFull);
    const float4* src = (const float4*)(emb + (size_t)v * T_DIM);
    float4* dst = (float4*)(out + (size_t)m * T_DIM);
    for (int i = threadIdx.x; i < T_DIM / 4; i += blockDim.x) dst[i] = src[i];
}

// ---------------- launcher ------------------------------------------------------
extern "C" void kernel_launch(void* const* d_in, const int* in_sizes, int n_in,
                              void* d_out, int out_size) {
    const float* audio = (const float*)d_in[0];   // [8,64,768]
    const float* W     = (const float*)d_in[1];   // [768,512]
    const float* b     = (const float*)d_in[2];   // [512]
    const float* emb   = (const float*)d_in[3];   // [49408,512]
    float* out         = (float*)d_out;           // [8,64,512]

    k_init<<<2, 256>>>();
    dim3 g1(T_DIM / 64, M_KW / 64);               // (8,8)
    k_proj<<<g1, 256>>>(audio, W, b);
    k_norms<<<V_SZ / 8, 256>>>(emb);
    dim3 g3(4, V_SZ / 128);                       // (4,386): m fastest for L2 reuse
    k_score<<<g3, 256>>>(emb);
    k_gather<<<M_KW, 128>>>(emb, out);
}

// round 3
// speedup vs baseline: 2.3324x; 2.3324x over previous
#include <cuda_runtime.h>
#include <cuda_bf16.h>
#include <cstdint>

#define M_KW 512
#define K_D  768
#define T_DIM 512
#define V_SZ 49408
#define EPSF 1e-8f

// GEMM tiling (mma.sync path)
#define BM 128
#define BN 128
#define BK 32                      // bf16 elems per k-step (64 B rows)
#define KCAT 1536                  // (hi,lo,hi) x (hi,hi,lo)
#define NKT (KCAT / BK)            // 48
#define NSTAGE 4
#define A_STG (BM * 64)            // 8192 B
#define B_STG (BN * 64)            // 8192 B
#define STG_BYTES (A_STG + B_STG)  // 16384
#define DSMEM (NSTAGE * STG_BYTES + 1024)

// ---------------- device scratch --------------------------------------------
__device__ __nv_bfloat16 g_Acat[M_KW * 1024];          // [512][hi(512)|lo(512)]
__device__ __nv_bfloat16 g_Bcat[(size_t)V_SZ * 1024];  // [49408][hi|lo], inv-norm folded
__device__ unsigned long long g_best[M_KW];

// ---------------- helpers ----------------------------------------------------
__device__ __forceinline__ uint32_t sptr(const void* p) {
    return (uint32_t)__cvta_generic_to_shared(p);
}
__device__ __forceinline__ unsigned fkey(float s) {
    unsigned u = __float_as_uint(s);
    return (u & 0x80000000u) ? ~u : (u | 0x80000000u);
}
__device__ __forceinline__ uint32_t swz64(uint32_t off) {   // 64B-row swizzle
    return off ^ ((off >> 3) & 0x30);
}
__device__ __forceinline__ void cpa16(uint32_t dst, const void* src) {
    asm volatile("cp.async.cg.shared.global [%0], [%1], 16;" :: "r"(dst), "l"(src));
}
__device__ __forceinline__ void ldsm4(uint32_t& r0, uint32_t& r1, uint32_t& r2,
                                      uint32_t& r3, uint32_t addr) {
    asm volatile("ldmatrix.sync.aligned.m8n8.x4.shared.b16 {%0,%1,%2,%3}, [%4];"
                 : "=r"(r0), "=r"(r1), "=r"(r2), "=r"(r3) : "r"(addr));
}
__device__ __forceinline__ void mma16816(float* c, const uint32_t* a,
                                         uint32_t b0, uint32_t b1) {
    asm volatile(
        "mma.sync.aligned.m16n8k16.row.col.f32.bf16.bf16.f32 "
        "{%0,%1,%2,%3}, {%4,%5,%6,%7}, {%8,%9}, {%0,%1,%2,%3};"
        : "+f"(c[0]), "+f"(c[1]), "+f"(c[2]), "+f"(c[3])
        : "r"(a[0]), "r"(a[1]), "r"(a[2]), "r"(a[3]), "r"(b0), "r"(b1));
}

// ---------------- K0: init argmax slots --------------------------------------
__global__ void k_init() {
    int i = blockIdx.x * blockDim.x + threadIdx.x;
    if (i < M_KW) g_best[i] = 0ull;
}

// ---------------- K1: proj (audio@W+b) -> A hi/lo bf16 ------------------------
__global__ __launch_bounds__(256) void k_proj(const float* __restrict__ A,
                                              const float* __restrict__ W,
                                              const float* __restrict__ b) {
    const int TBM = 64, TBN = 64, TBK = 16;
    __shared__ float As[TBK][TBM + 4];
    __shared__ float Ws[TBK][TBN];
    int tid = threadIdx.x;
    int tx = tid & 15, ty = tid >> 4;
    int n0 = blockIdx.x * TBN, m0 = blockIdx.y * TBM;
    float acc[4][4] = {};
    for (int k0 = 0; k0 < K_D; k0 += TBK) {
        #pragma unroll
        for (int i = 0; i < 4; ++i) {
            int idx = tid + i * 256;
            int r = idx >> 4, kk = idx & 15;
            As[kk][r] = A[(m0 + r) * K_D + k0 + kk];
        }
        #pragma unroll
        for (int i = 0; i < 4; ++i) {
            int idx = tid + i * 256;
            int kk = idx >> 6, n = idx & 63;
            Ws[kk][n] = W[(k0 + kk) * T_DIM + n0 + n];
        }
        __syncthreads();
        #pragma unroll
        for (int kk = 0; kk < TBK; ++kk) {
            float av[4], bv[4];
            #pragma unroll
            for (int i = 0; i < 4; ++i) av[i] = As[kk][ty * 4 + i];
            #pragma unroll
            for (int j = 0; j < 4; ++j) bv[j] = Ws[kk][tx * 4 + j];
            #pragma unroll
            for (int i = 0; i < 4; ++i)
                #pragma unroll
                for (int j = 0; j < 4; ++j)
                    acc[i][j] = fmaf(av[i], bv[j], acc[i][j]);
        }
        __syncthreads();
    }
    #pragma unroll
    for (int i = 0; i < 4; ++i) {
        int m = m0 + ty * 4 + i;
        int n = n0 + tx * 4;
        __nv_bfloat16 hi[4], lo[4];
        #pragma unroll
        for (int j = 0; j < 4; ++j) {
            float x = acc[i][j] + b[n + j];
            hi[j] = __float2bfloat16(x);
            lo[j] = __float2bfloat16(x - __bfloat162float(hi[j]));
        }
        *(uint2*)&g_Acat[(size_t)m * 1024 + n]       = *(uint2*)hi;
        *(uint2*)&g_Acat[(size_t)m * 1024 + 512 + n] = *(uint2*)lo;
    }
}

// ---------------- K2: emb -> normalized hi/lo bf16 ----------------------------
__global__ __launch_bounds__(256) void k_prepB(const float* __restrict__ emb) {
    int v = blockIdx.x * 8 + (threadIdx.x >> 5);
    int lane = threadIdx.x & 31;
    const float4* p = (const float4*)(emb + (size_t)v * T_DIM);
    float4 vals[4];
    float ss = 0.f;
    #pragma unroll
    for (int i = 0; i < 4; ++i) {
        vals[i] = p[lane + i * 32];
        ss += vals[i].x * vals[i].x + vals[i].y * vals[i].y
            + vals[i].z * vals[i].z + vals[i].w * vals[i].w;
    }
    #pragma unroll
    for (int o = 16; o; o >>= 1) ss += __shfl_xor_sync(0xffffffffu, ss, o);
    float inv = 1.0f / fmaxf(sqrtf(ss), EPSF);
    #pragma unroll
    for (int i = 0; i < 4; ++i) {
        float x[4] = {vals[i].x * inv, vals[i].y * inv, vals[i].z * inv, vals[i].w * inv};
        __nv_bfloat16 hi[4], lo[4];
        #pragma unroll
        for (int j = 0; j < 4; ++j) {
            hi[j] = __float2bfloat16(x[j]);
            lo[j] = __float2bfloat16(x[j] - __bfloat162float(hi[j]));
        }
        int idx = (lane + i * 32) * 4;
        *(uint2*)&g_Bcat[(size_t)v * 1024 + idx]       = *(uint2*)hi;
        *(uint2*)&g_Bcat[(size_t)v * 1024 + 512 + idx] = *(uint2*)lo;
    }
}

// ---------------- K3: mma.sync score GEMM + fused argmax ----------------------
__device__ __forceinline__ void fill_stage(uint32_t stg, int m0, int n0, int kt, int tid) {
    int kb = kt >> 4, ki = kt & 15;
    int ka = ((kb == 1) ? 512 : 0) + ki * 32;      // A blocks: hi, lo, hi
    int kbo = ((kb == 2) ? 512 : 0) + ki * 32;     // B blocks: hi, hi, lo
    #pragma unroll
    for (int i = 0; i < 4; ++i) {                  // A: 512 chunks of 16B
        int c = tid + i * 128;
        int r = c >> 2, cc = c & 3;
        cpa16(stg + swz64(r * 64 + cc * 16),
              &g_Acat[(size_t)(m0 + r) * 1024 + ka + cc * 8]);
    }
    #pragma unroll
    for (int i = 0; i < 4; ++i) {                  // B: 512 chunks of 16B
        int c = tid + i * 128;
        int r = c >> 2, cc = c & 3;
        cpa16(stg + A_STG + swz64(r * 64 + cc * 16),
              &g_Bcat[(size_t)(n0 + r) * 1024 + kbo + cc * 8]);
    }
    asm volatile("cp.async.commit_group;" ::: "memory");
}

__global__ __launch_bounds__(128, 2) void k_score() {
    extern __shared__ __align__(16) char smraw[];
    uint32_t sm0 = (sptr(smraw) + 1023) & ~1023u;
    int tid = threadIdx.x;
    int wid = tid >> 5, lane = tid & 31;
    int warp_m = wid & 1, warp_n = wid >> 1;       // 2x2 warp grid, 64x64 tiles
    int m0 = blockIdx.x * BM;
    int n0 = blockIdx.y * BN;

    float acc[4][8][4];
    #pragma unroll
    for (int i = 0; i < 4; ++i)
        #pragma unroll
        for (int j = 0; j < 8; ++j)
            #pragma unroll
            for (int k = 0; k < 4; ++k) acc[i][j][k] = 0.f;

    // prologue: fill stages 0..2
    #pragma unroll
    for (int p = 0; p < NSTAGE - 1; ++p)
        fill_stage(sm0 + p * STG_BYTES, m0, n0, p, tid);

    // precomputed intra-tile address components
    int aRow = warp_m * 64 + (lane & 15);          // + mb*16
    int aHi  = ((lane >> 4) & 1) * 16;
    int bRow = warp_n * 64 + ((lane >> 4) & 1) * 8 + (lane & 7);  // + nbb*16
    int bHi  = ((lane >> 3) & 1) * 16;

    for (int kt = 0; kt < NKT; ++kt) {
        asm volatile("cp.async.wait_group 2;" ::: "memory");
        __syncthreads();
        int fk = kt + NSTAGE - 1;
        if (fk < NKT)
            fill_stage(sm0 + (fk & 3) * STG_BYTES, m0, n0, fk, tid);

        uint32_t Ab = sm0 + (kt & 3) * STG_BYTES;
        uint32_t Bb = Ab + A_STG;
        #pragma unroll
        for (int half = 0; half < 2; ++half) {
            uint32_t a[4][4], b[4][4];
            #pragma unroll
            for (int mb = 0; mb < 4; ++mb)
                ldsm4(a[mb][0], a[mb][1], a[mb][2], a[mb][3],
                      Ab + swz64((aRow + mb * 16) * 64 + half * 32 + aHi));
            #pragma unroll
            for (int nbb = 0; nbb < 4; ++nbb)
                ldsm4(b[nbb][0], b[nbb][1], b[nbb][2], b[nbb][3],
                      Bb + swz64((bRow + nbb * 16) * 64 + half * 32 + bHi));
            #pragma unroll
            for (int mb = 0; mb < 4; ++mb)
                #pragma unroll
                for (int nbb = 0; nbb < 4; ++nbb) {
                    mma16816(acc[mb][2 * nbb],     a[mb], b[nbb][0], b[nbb][1]);
                    mma16816(acc[mb][2 * nbb + 1], a[mb], b[nbb][2], b[nbb][3]);
                }
        }
        __syncthreads();
    }

    // ---- epilogue: argmax ----
    // acc[mb][nb]: c0,c1 -> row mb*16 + lane/4, cols nb*8 + (lane%4)*2 + {0,1}
    //              c2,c3 -> row +8, same cols
    unsigned long long* red = (unsigned long long*)smraw;   // [BM][2]
    #pragma unroll
    for (int mb = 0; mb < 4; ++mb) {
        #pragma unroll
        for (int half = 0; half < 2; ++half) {               // row, row+8
            float bs = -3.0e38f; int bn = 0;
            #pragma unroll
            for (int nb = 0; nb < 8; ++nb) {
                #pragma unroll
                for (int j = 0; j < 2; ++j) {
                    float s = acc[mb][nb][half * 2 + j];
                    if (s > bs) { bs = s; bn = nb * 8 + (lane & 3) * 2 + j; }
                }
            }
            unsigned v = (unsigned)(n0 + warp_n * 64 + bn);
            unsigned long long pk =
                ((unsigned long long)fkey(bs) << 32) | (0xFFFFFFFFu - v);
            #pragma unroll
            for (int o = 1; o <= 2; o <<= 1) {
                unsigned long long x = __shfl_xor_sync(0xffffffffu, pk, o);
                if (x > pk) pk = x;
            }
            if ((lane & 3) == 0) {
                int row = warp_m * 64 + mb * 16 + half * 8 + (lane >> 2);
                red[row * 2 + warp_n] = pk;
            }
        }
    }
    __syncthreads();
    if (tid < 128) {
        unsigned long long a0 = red[tid * 2], a1 = red[tid * 2 + 1];
        atomicMax(&g_best[m0 + tid], a0 > a1 ? a0 : a1);
    }
}

// ---------------- K4: gather selected embeddings -------------------------------
__global__ void k_gather(const float* __restrict__ emb, float* __restrict__ out) {
    int m = blockIdx.x;
    unsigned v = 0xFFFFFFFFu - (unsigned)(g_best[m] & 0xFFFFFFFFull);
    const float4* src = (const float4*)(emb + (size_t)v * T_DIM);
    float4* dst = (float4*)(out + (size_t)m * T_DIM);
    for (int i = threadIdx.x; i < T_DIM / 4; i += blockDim.x) dst[i] = src[i];
}

// ---------------- launcher ------------------------------------------------------
extern "C" void kernel_launch(void* const* d_in, const int* in_sizes, int n_in,
                              void* d_out, int out_size) {
    const float* audio = (const float*)d_in[0];
    const float* W     = (const float*)d_in[1];
    const float* b     = (const float*)d_in[2];
    const float* emb   = (const float*)d_in[3];
    float* out         = (float*)d_out;

    cudaFuncSetAttribute(k_score, cudaFuncAttributeMaxDynamicSharedMemorySize, DSMEM);

    k_init<<<2, 256>>>();
    dim3 g1(T_DIM / 64, M_KW / 64);
    k_proj<<<g1, 256>>>(audio, W, b);
    k_prepB<<<V_SZ / 8, 256>>>(emb);
    dim3 g3(M_KW / BM, V_SZ / BN);      // (4, 386): x fastest -> B tile L2 reuse
    k_score<<<g3, 128, DSMEM>>>();
    k_gather<<<M_KW, 128>>>(emb, out);
}

// round 4
// speedup vs baseline: 2.4776x; 1.0623x over previous
#include <cuda_runtime.h>
#include <cuda_bf16.h>
#include <cstdint>

#define M_KW 512
#define K_D  768
#define T_DIM 512
#define V_SZ 49408
#define EPSF 1e-8f

// pass-1 GEMM tiling (proven R3 mainloop, K now 512)
#define BM 128
#define BN 128
#define BK 32
#define NKT (T_DIM / BK)           // 16
#define NSTAGE 4
#define A_STG (BM * 64)
#define B_STG (BN * 64)
#define STG_BYTES (A_STG + B_STG)  // 16384
#define DSMEM (NSTAGE * STG_BYTES + 1024)

// ---------------- device scratch ------------------------------------------------
__device__ float g_kw[M_KW * T_DIM];                   // fp32 projected keywords
__device__ __nv_bfloat16 g_A16[M_KW * T_DIM];          // bf16(hi) of g_kw
__device__ __nv_bfloat16 g_B16[(size_t)V_SZ * T_DIM];  // bf16(hi) of normalized emb
__device__ float g_invn[V_SZ];                         // 1/max(||emb_v||,eps)
__device__ float g_scores[(size_t)M_KW * V_SZ];        // pass-1 hi scores (101 MB)
__device__ float g_margin[M_KW];                       // 0.0085*||kw_m||
__device__ unsigned g_hikey[M_KW];                     // fkey(max hi score)
__device__ unsigned long long g_best[M_KW];            // packed exact argmax

// ---------------- helpers -------------------------------------------------------
__device__ __forceinline__ uint32_t sptr(const void* p) {
    return (uint32_t)__cvta_generic_to_shared(p);
}
__device__ __forceinline__ unsigned fkey(float s) {
    unsigned u = __float_as_uint(s);
    return (u & 0x80000000u) ? ~u : (u | 0x80000000u);
}
__device__ __forceinline__ float unfkey(unsigned k) {
    return (k & 0x80000000u) ? __uint_as_float(k ^ 0x80000000u) : __uint_as_float(~k);
}
__device__ __forceinline__ uint32_t swz64(uint32_t off) {
    return off ^ ((off >> 3) & 0x30);
}
__device__ __forceinline__ void cpa16(uint32_t dst, const void* src) {
    asm volatile("cp.async.cg.shared.global [%0], [%1], 16;" :: "r"(dst), "l"(src));
}
__device__ __forceinline__ void ldsm4(uint32_t& r0, uint32_t& r1, uint32_t& r2,
                                      uint32_t& r3, uint32_t addr) {
    asm volatile("ldmatrix.sync.aligned.m8n8.x4.shared.b16 {%0,%1,%2,%3}, [%4];"
                 : "=r"(r0), "=r"(r1), "=r"(r2), "=r"(r3) : "r"(addr));
}
__device__ __forceinline__ void mma16816(float* c, const uint32_t* a,
                                         uint32_t b0, uint32_t b1) {
    asm volatile(
        "mma.sync.aligned.m16n8k16.row.col.f32.bf16.bf16.f32 "
        "{%0,%1,%2,%3}, {%4,%5,%6,%7}, {%8,%9}, {%0,%1,%2,%3};"
        : "+f"(c[0]), "+f"(c[1]), "+f"(c[2]), "+f"(c[3])
        : "r"(a[0]), "r"(a[1]), "r"(a[2]), "r"(a[3]), "r"(b0), "r"(b1));
}

// ---------------- K0: init ------------------------------------------------------
__global__ void k_init() {
    int i = blockIdx.x * blockDim.x + threadIdx.x;
    if (i < M_KW) { g_best[i] = 0ull; g_hikey[i] = 0u; }
}

// ---------------- K1: proj -> g_kw fp32 + g_A16 bf16 ----------------------------
__global__ __launch_bounds__(256) void k_proj(const float* __restrict__ A,
                                              const float* __restrict__ W,
                                              const float* __restrict__ b) {
    const int TBM = 64, TBN = 64, TBK = 16;
    __shared__ float As[TBK][TBM + 4];
    __shared__ float Ws[TBK][TBN];
    int tid = threadIdx.x;
    int tx = tid & 15, ty = tid >> 4;
    int n0 = blockIdx.x * TBN, m0 = blockIdx.y * TBM;
    float acc[4][4] = {};
    for (int k0 = 0; k0 < K_D; k0 += TBK) {
        #pragma unroll
        for (int i = 0; i < 4; ++i) {
            int idx = tid + i * 256;
            int r = idx >> 4, kk = idx & 15;
            As[kk][r] = A[(m0 + r) * K_D + k0 + kk];
        }
        #pragma unroll
        for (int i = 0; i < 4; ++i) {
            int idx = tid + i * 256;
            int kk = idx >> 6, n = idx & 63;
            Ws[kk][n] = W[(k0 + kk) * T_DIM + n0 + n];
        }
        __syncthreads();
        #pragma unroll
        for (int kk = 0; kk < TBK; ++kk) {
            float av[4], bv[4];
            #pragma unroll
            for (int i = 0; i < 4; ++i) av[i] = As[kk][ty * 4 + i];
            #pragma unroll
            for (int j = 0; j < 4; ++j) bv[j] = Ws[kk][tx * 4 + j];
            #pragma unroll
            for (int i = 0; i < 4; ++i)
                #pragma unroll
                for (int j = 0; j < 4; ++j)
                    acc[i][j] = fmaf(av[i], bv[j], acc[i][j]);
        }
        __syncthreads();
    }
    #pragma unroll
    for (int i = 0; i < 4; ++i) {
        int m = m0 + ty * 4 + i;
        int n = n0 + tx * 4;
        float x[4];
        __nv_bfloat16 hi[4];
        #pragma unroll
        for (int j = 0; j < 4; ++j) {
            x[j] = acc[i][j] + b[n + j];
            hi[j] = __float2bfloat16(x[j]);
        }
        *(float4*)&g_kw[(size_t)m * T_DIM + n] = *(float4*)x;
        *(uint2*)&g_A16[(size_t)m * T_DIM + n] = *(uint2*)hi;
    }
}

// ---------------- K1b: per-keyword margin = 0.0085*||kw|| ----------------------
__global__ __launch_bounds__(256) void k_anorm() {
    int row = blockIdx.x * 8 + (threadIdx.x >> 5);
    int lane = threadIdx.x & 31;
    const float4* p = (const float4*)(g_kw + (size_t)row * T_DIM);
    float ss = 0.f;
    #pragma unroll
    for (int i = 0; i < 4; ++i) {
        float4 v = p[lane + i * 32];
        ss += v.x * v.x + v.y * v.y + v.z * v.z + v.w * v.w;
    }
    #pragma unroll
    for (int o = 16; o; o >>= 1) ss += __shfl_xor_sync(0xffffffffu, ss, o);
    if (lane == 0) g_margin[row] = 0.0085f * sqrtf(ss);
}

// ---------------- K2: emb -> normalized bf16(hi) + invn -------------------------
__global__ __launch_bounds__(256) void k_prepB(const float* __restrict__ emb) {
    int v = blockIdx.x * 8 + (threadIdx.x >> 5);
    int lane = threadIdx.x & 31;
    const float4* p = (const float4*)(emb + (size_t)v * T_DIM);
    float4 vals[4];
    float ss = 0.f;
    #pragma unroll
    for (int i = 0; i < 4; ++i) {
        vals[i] = p[lane + i * 32];
        ss += vals[i].x * vals[i].x + vals[i].y * vals[i].y
            + vals[i].z * vals[i].z + vals[i].w * vals[i].w;
    }
    #pragma unroll
    for (int o = 16; o; o >>= 1) ss += __shfl_xor_sync(0xffffffffu, ss, o);
    float inv = 1.0f / fmaxf(sqrtf(ss), EPSF);
    if (lane == 0) g_invn[v] = inv;
    #pragma unroll
    for (int i = 0; i < 4; ++i) {
        __nv_bfloat16 hi[4];
        hi[0] = __float2bfloat16(vals[i].x * inv);
        hi[1] = __float2bfloat16(vals[i].y * inv);
        hi[2] = __float2bfloat16(vals[i].z * inv);
        hi[3] = __float2bfloat16(vals[i].w * inv);
        int idx = (lane + i * 32) * 4;
        *(uint2*)&g_B16[(size_t)v * T_DIM + idx] = *(uint2*)hi;
    }
}

// ---------------- K3: pass1 — hi GEMM, store scores, track hi max ---------------
__device__ __forceinline__ void fill_stage(uint32_t stg, int m0, int n0, int kt, int tid) {
    int kk = kt * 32;
    #pragma unroll
    for (int i = 0; i < 4; ++i) {
        int c = tid + i * 128;
        int r = c >> 2, cc = c & 3;
        cpa16(stg + swz64(r * 64 + cc * 16),
              &g_A16[(size_t)(m0 + r) * T_DIM + kk + cc * 8]);
    }
    #pragma unroll
    for (int i = 0; i < 4; ++i) {
        int c = tid + i * 128;
        int r = c >> 2, cc = c & 3;
        cpa16(stg + A_STG + swz64(r * 64 + cc * 16),
              &g_B16[(size_t)(n0 + r) * T_DIM + kk + cc * 8]);
    }
    asm volatile("cp.async.commit_group;" ::: "memory");
}

__global__ __launch_bounds__(128, 2) void k_pass1() {
    extern __shared__ __align__(16) char smraw[];
    uint32_t sm0 = (sptr(smraw) + 1023) & ~1023u;
    int tid = threadIdx.x;
    int lane = tid & 31, wid = tid >> 5;
    int warp_m = wid & 1, warp_n = wid >> 1;
    int m0 = blockIdx.x * BM;
    int n0 = blockIdx.y * BN;

    float acc[4][8][4];
    #pragma unroll
    for (int i = 0; i < 4; ++i)
        #pragma unroll
        for (int j = 0; j < 8; ++j)
            #pragma unroll
            for (int k = 0; k < 4; ++k) acc[i][j][k] = 0.f;

    #pragma unroll
    for (int p = 0; p < NSTAGE - 1; ++p)
        fill_stage(sm0 + p * STG_BYTES, m0, n0, p, tid);

    int aRow = warp_m * 64 + (lane & 15);
    int aHi  = ((lane >> 4) & 1) * 16;
    int bRow = warp_n * 64 + ((lane >> 4) & 1) * 8 + (lane & 7);
    int bHi  = ((lane >> 3) & 1) * 16;

    for (int kt = 0; kt < NKT; ++kt) {
        asm volatile("cp.async.wait_group 2;" ::: "memory");
        __syncthreads();
        int fk = kt + NSTAGE - 1;
        if (fk < NKT)
            fill_stage(sm0 + (fk & 3) * STG_BYTES, m0, n0, fk, tid);

        uint32_t Ab = sm0 + (kt & 3) * STG_BYTES;
        uint32_t Bb = Ab + A_STG;
        #pragma unroll
        for (int half = 0; half < 2; ++half) {
            uint32_t a[4][4], b[4][4];
            #pragma unroll
            for (int mb = 0; mb < 4; ++mb)
                ldsm4(a[mb][0], a[mb][1], a[mb][2], a[mb][3],
                      Ab + swz64((aRow + mb * 16) * 64 + half * 32 + aHi));
            #pragma unroll
            for (int nbb = 0; nbb < 4; ++nbb)
                ldsm4(b[nbb][0], b[nbb][1], b[nbb][2], b[nbb][3],
                      Bb + swz64((bRow + nbb * 16) * 64 + half * 32 + bHi));
            #pragma unroll
            for (int mb = 0; mb < 4; ++mb)
                #pragma unroll
                for (int nbb = 0; nbb < 4; ++nbb) {
                    mma16816(acc[mb][2 * nbb],     a[mb], b[nbb][0], b[nbb][1]);
                    mma16816(acc[mb][2 * nbb + 1], a[mb], b[nbb][2], b[nbb][3]);
                }
        }
        __syncthreads();
    }

    // epilogue: store scores + per-row hi-max atomic
    #pragma unroll
    for (int mb = 0; mb < 4; ++mb) {
        #pragma unroll
        for (int half = 0; half < 2; ++half) {
            int row = m0 + warp_m * 64 + mb * 16 + half * 8 + (lane >> 2);
            float bs = -3.0e38f;
            #pragma unroll
            for (int nb = 0; nb < 8; ++nb) {
                float s0 = acc[mb][nb][half * 2];
                float s1 = acc[mb][nb][half * 2 + 1];
                float2 st = make_float2(s0, s1);
                *(float2*)&g_scores[(size_t)row * V_SZ + n0 + warp_n * 64 +
                                    nb * 8 + (lane & 3) * 2] = st;
                bs = fmaxf(bs, fmaxf(s0, s1));
            }
            unsigned pk = fkey(bs);
            #pragma unroll
            for (int o = 1; o <= 2; o <<= 1)
                pk = max(pk, __shfl_xor_sync(0xffffffffu, pk, o));
            if ((lane & 3) == 0) atomicMax(&g_hikey[row], pk);
        }
    }
}

// ---------------- K4: pass2 — scan + exact fp32 rescore of candidates ----------
__global__ __launch_bounds__(256) void k_pass2(const float* __restrict__ emb) {
    int m = blockIdx.x;
    float thr = unfkey(g_hikey[m]) - g_margin[m];
    const float4* row = (const float4*)(g_scores + (size_t)m * V_SZ);
    const float4* kwr = (const float4*)(g_kw + (size_t)m * T_DIM);

    for (int v4 = threadIdx.x; v4 < V_SZ / 4; v4 += 256) {
        float4 s = row[v4];
        #pragma unroll
        for (int j = 0; j < 4; ++j) {
            float sv = (j == 0) ? s.x : (j == 1) ? s.y : (j == 2) ? s.z : s.w;
            if (sv >= thr) {
                int v = v4 * 4 + j;
                const float4* er = (const float4*)(emb + (size_t)v * T_DIM);
                float dot = 0.f;
                #pragma unroll 4
                for (int i = 0; i < T_DIM / 4; ++i) {
                    float4 a = kwr[i], bb = er[i];
                    dot = fmaf(a.x, bb.x, dot);
                    dot = fmaf(a.y, bb.y, dot);
                    dot = fmaf(a.z, bb.z, dot);
                    dot = fmaf(a.w, bb.w, dot);
                }
                float ex = dot * g_invn[v];
                unsigned long long pk =
                    ((unsigned long long)fkey(ex) << 32) | (0xFFFFFFFFu - (unsigned)v);
                atomicMax(&g_best[m], pk);
            }
        }
    }
}

// ---------------- K5: gather -----------------------------------------------------
__global__ void k_gather(const float* __restrict__ emb, float* __restrict__ out) {
    int m = blockIdx.x;
    unsigned v = 0xFFFFFFFFu - (unsigned)(g_best[m] & 0xFFFFFFFFull);
    const float4* src = (const float4*)(emb + (size_t)v * T_DIM);
    float4* dst = (float4*)(out + (size_t)m * T_DIM);
    for (int i = threadIdx.x; i < T_DIM / 4; i += blockDim.x) dst[i] = src[i];
}

// ---------------- launcher --------------------------------------------------------
extern "C" void kernel_launch(void* const* d_in, const int* in_sizes, int n_in,
                              void* d_out, int out_size) {
    const float* audio = (const float*)d_in[0];
    const float* W     = (const float*)d_in[1];
    const float* b     = (const float*)d_in[2];
    const float* emb   = (const float*)d_in[3];
    float* out         = (float*)d_out;

    cudaFuncSetAttribute(k_pass1, cudaFuncAttributeMaxDynamicSharedMemorySize, DSMEM);

    k_init<<<2, 256>>>();
    dim3 g1(T_DIM / 64, M_KW / 64);
    k_proj<<<g1, 256>>>(audio, W, b);
    k_anorm<<<M_KW / 8, 256>>>();
    k_prepB<<<V_SZ / 8, 256>>>(emb);
    dim3 g3(M_KW / BM, V_SZ / BN);       // (4, 386)
    k_pass1<<<g3, 128, DSMEM>>>();
    k_pass2<<<M_KW, 256>>>(emb);
    k_gather<<<M_KW, 128>>>(emb, out);
}

// round 5
// speedup vs baseline: 3.5183x; 1.4200x over previous
#include <cuda_runtime.h>
#include <cuda_bf16.h>
#include <cstdint>

#define M_KW 512
#define K_D  768
#define T_DIM 512
#define V_SZ 49408
#define NTILE (V_SZ / 128)         // 386
#define EPSF 1e-8f

// pass-1 GEMM tiling
#define BM 128
#define BN 128
#define BK 32
#define NKT (T_DIM / BK)           // 16
#define NSTAGE 4
#define A_STG (BM * 64)
#define B_STG (BN * 64)
#define STG_BYTES (A_STG + B_STG)  // 16384
#define DSMEM (NSTAGE * STG_BYTES + 1024)

// ---------------- device scratch ------------------------------------------------
__device__ float g_kw[M_KW * T_DIM];                       // fp32 projected keywords
__device__ __nv_bfloat16 g_A16[M_KW * T_DIM];              // bf16 of g_kw
__device__ __nv_bfloat16 g_B16[(size_t)V_SZ * T_DIM];      // bf16 normalized emb
__device__ float g_invn[V_SZ];                             // 1/max(||emb_v||,eps)
__device__ __nv_bfloat16 g_s16[(size_t)M_KW * V_SZ];       // bf16 hi scores (50 MB)
__device__ float g_tilemax[(size_t)M_KW * NTILE];          // per-row per-tile max
__device__ float g_msq[M_KW];                              // ||kw_m||^2 (atomicAdd)
__device__ unsigned g_hikey[M_KW];                         // fkey(max bf16 score)
__device__ unsigned long long g_best[M_KW];                // packed exact argmax

// ---------------- helpers -------------------------------------------------------
__device__ __forceinline__ uint32_t sptr(const void* p) {
    return (uint32_t)__cvta_generic_to_shared(p);
}
__device__ __forceinline__ unsigned fkey(float s) {
    unsigned u = __float_as_uint(s);
    return (u & 0x80000000u) ? ~u : (u | 0x80000000u);
}
__device__ __forceinline__ float unfkey(unsigned k) {
    return (k & 0x80000000u) ? __uint_as_float(k ^ 0x80000000u) : __uint_as_float(~k);
}
__device__ __forceinline__ uint32_t swz64(uint32_t off) {
    return off ^ ((off >> 3) & 0x30);
}
__device__ __forceinline__ void cpa16(uint32_t dst, const void* src) {
    asm volatile("cp.async.cg.shared.global [%0], [%1], 16;" :: "r"(dst), "l"(src));
}
__device__ __forceinline__ void ldsm4(uint32_t& r0, uint32_t& r1, uint32_t& r2,
                                      uint32_t& r3, uint32_t addr) {
    asm volatile("ldmatrix.sync.aligned.m8n8.x4.shared.b16 {%0,%1,%2,%3}, [%4];"
                 : "=r"(r0), "=r"(r1), "=r"(r2), "=r"(r3) : "r"(addr));
}
__device__ __forceinline__ void mma16816(float* c, const uint32_t* a,
                                         uint32_t b0, uint32_t b1) {
    asm volatile(
        "mma.sync.aligned.m16n8k16.row.col.f32.bf16.bf16.f32 "
        "{%0,%1,%2,%3}, {%4,%5,%6,%7}, {%8,%9}, {%0,%1,%2,%3};"
        : "+f"(c[0]), "+f"(c[1]), "+f"(c[2]), "+f"(c[3])
        : "r"(a[0]), "r"(a[1]), "r"(a[2]), "r"(a[3]), "r"(b0), "r"(b1));
}
__device__ __forceinline__ float warp_dot(const float4* kr, const float4* er, int lane) {
    float d0 = 0.f, d1 = 0.f;
    #pragma unroll
    for (int i = 0; i < 4; i += 2) {
        float4 a0 = kr[lane + i * 32],       b0 = er[lane + i * 32];
        float4 a1 = kr[lane + (i + 1) * 32], b1 = er[lane + (i + 1) * 32];
        d0 = fmaf(a0.x, b0.x, d0); d0 = fmaf(a0.y, b0.y, d0);
        d0 = fmaf(a0.z, b0.z, d0); d0 = fmaf(a0.w, b0.w, d0);
        d1 = fmaf(a1.x, b1.x, d1); d1 = fmaf(a1.y, b1.y, d1);
        d1 = fmaf(a1.z, b1.z, d1); d1 = fmaf(a1.w, b1.w, d1);
    }
    float d = d0 + d1;
    #pragma unroll
    for (int o = 16; o; o >>= 1) d += __shfl_xor_sync(0xffffffffu, d, o);
    return d;
}

// ---------------- K0: init ------------------------------------------------------
__global__ void k_init() {
    int i = blockIdx.x * blockDim.x + threadIdx.x;
    if (i < M_KW) { g_best[i] = 0ull; g_hikey[i] = 0u; g_msq[i] = 0.f; }
}

// ---------------- K1: proj -> g_kw fp32 + g_A16 bf16 + row sumsq ----------------
__global__ __launch_bounds__(256) void k_proj(const float* __restrict__ A,
                                              const float* __restrict__ W,
                                              const float* __restrict__ b) {
    const int TBM = 64, TBN = 64, TBK = 16;
    __shared__ float As[TBK][TBM + 4];
    __shared__ float Ws[TBK][TBN];
    int tid = threadIdx.x;
    int tx = tid & 15, ty = tid >> 4;
    int n0 = blockIdx.x * TBN, m0 = blockIdx.y * TBM;
    float acc[4][4] = {};
    for (int k0 = 0; k0 < K_D; k0 += TBK) {
        #pragma unroll
        for (int i = 0; i < 4; ++i) {
            int idx = tid + i * 256;
            int r = idx >> 4, kk = idx & 15;
            As[kk][r] = A[(m0 + r) * K_D + k0 + kk];
        }
        #pragma unroll
        for (int i = 0; i < 4; ++i) {
            int idx = tid + i * 256;
            int kk = idx >> 6, n = idx & 63;
            Ws[kk][n] = W[(k0 + kk) * T_DIM + n0 + n];
        }
        __syncthreads();
        #pragma unroll
        for (int kk = 0; kk < TBK; ++kk) {
            float av[4], bv[4];
            #pragma unroll
            for (int i = 0; i < 4; ++i) av[i] = As[kk][ty * 4 + i];
            #pragma unroll
            for (int j = 0; j < 4; ++j) bv[j] = Ws[kk][tx * 4 + j];
            #pragma unroll
            for (int i = 0; i < 4; ++i)
                #pragma unroll
                for (int j = 0; j < 4; ++j)
                    acc[i][j] = fmaf(av[i], bv[j], acc[i][j]);
        }
        __syncthreads();
    }
    #pragma unroll
    for (int i = 0; i < 4; ++i) {
        int m = m0 + ty * 4 + i;
        int n = n0 + tx * 4;
        float x[4];
        __nv_bfloat16 hi[4];
        float rp = 0.f;
        #pragma unroll
        for (int j = 0; j < 4; ++j) {
            x[j] = acc[i][j] + b[n + j];
            hi[j] = __float2bfloat16(x[j]);
            rp = fmaf(x[j], x[j], rp);
        }
        *(float4*)&g_kw[(size_t)m * T_DIM + n] = *(float4*)x;
        *(uint2*)&g_A16[(size_t)m * T_DIM + n] = *(uint2*)hi;
        #pragma unroll
        for (int o = 1; o < 16; o <<= 1)
            rp += __shfl_xor_sync(0xffffffffu, rp, o);
        if (tx == 0) atomicAdd(&g_msq[m], rp);
    }
}

// ---------------- K2: emb -> normalized bf16 + invn -----------------------------
__global__ __launch_bounds__(256) void k_prepB(const float* __restrict__ emb) {
    int v = blockIdx.x * 8 + (threadIdx.x >> 5);
    int lane = threadIdx.x & 31;
    const float4* p = (const float4*)(emb + (size_t)v * T_DIM);
    float4 vals[4];
    float ss = 0.f;
    #pragma unroll
    for (int i = 0; i < 4; ++i) {
        vals[i] = p[lane + i * 32];
        ss += vals[i].x * vals[i].x + vals[i].y * vals[i].y
            + vals[i].z * vals[i].z + vals[i].w * vals[i].w;
    }
    #pragma unroll
    for (int o = 16; o; o >>= 1) ss += __shfl_xor_sync(0xffffffffu, ss, o);
    float inv = 1.0f / fmaxf(sqrtf(ss), EPSF);
    if (lane == 0) g_invn[v] = inv;
    #pragma unroll
    for (int i = 0; i < 4; ++i) {
        __nv_bfloat16 hi[4];
        hi[0] = __float2bfloat16(vals[i].x * inv);
        hi[1] = __float2bfloat16(vals[i].y * inv);
        hi[2] = __float2bfloat16(vals[i].z * inv);
        hi[3] = __float2bfloat16(vals[i].w * inv);
        int idx = (lane + i * 32) * 4;
        *(uint2*)&g_B16[(size_t)v * T_DIM + idx] = *(uint2*)hi;
    }
}

// ---------------- K3: pass1 — bf16 GEMM, bf16 scores + tile maxima --------------
__device__ __forceinline__ void fill_stage(uint32_t stg, int m0, int n0, int kt, int tid) {
    int kk = kt * 32;
    #pragma unroll
    for (int i = 0; i < 4; ++i) {
        int c = tid + i * 128;
        int r = c >> 2, cc = c & 3;
        cpa16(stg + swz64(r * 64 + cc * 16),
              &g_A16[(size_t)(m0 + r) * T_DIM + kk + cc * 8]);
    }
    #pragma unroll
    for (int i = 0; i < 4; ++i) {
        int c = tid + i * 128;
        int r = c >> 2, cc = c & 3;
        cpa16(stg + A_STG + swz64(r * 64 + cc * 16),
              &g_B16[(size_t)(n0 + r) * T_DIM + kk + cc * 8]);
    }
    asm volatile("cp.async.commit_group;" ::: "memory");
}

__global__ __launch_bounds__(128, 2) void k_pass1() {
    extern __shared__ __align__(16) char smraw[];
    uint32_t sm0 = (sptr(smraw) + 1023) & ~1023u;
    int tid = threadIdx.x;
    int lane = tid & 31, wid = tid >> 5;
    int warp_m = wid & 1, warp_n = wid >> 1;
    int m0 = blockIdx.x * BM;
    int n0 = blockIdx.y * BN;

    float acc[4][8][4];
    #pragma unroll
    for (int i = 0; i < 4; ++i)
        #pragma unroll
        for (int j = 0; j < 8; ++j)
            #pragma unroll
            for (int k = 0; k < 4; ++k) acc[i][j][k] = 0.f;

    #pragma unroll
    for (int p = 0; p < NSTAGE - 1; ++p)
        fill_stage(sm0 + p * STG_BYTES, m0, n0, p, tid);

    int aRow = warp_m * 64 + (lane & 15);
    int aHi  = ((lane >> 4) & 1) * 16;
    int bRow = warp_n * 64 + ((lane >> 4) & 1) * 8 + (lane & 7);
    int bHi  = ((lane >> 3) & 1) * 16;

    for (int kt = 0; kt < NKT; ++kt) {
        asm volatile("cp.async.wait_group 2;" ::: "memory");
        __syncthreads();
        int fk = kt + NSTAGE - 1;
        if (fk < NKT)
            fill_stage(sm0 + (fk & 3) * STG_BYTES, m0, n0, fk, tid);

        uint32_t Ab = sm0 + (kt & 3) * STG_BYTES;
        uint32_t Bb = Ab + A_STG;
        #pragma unroll
        for (int half = 0; half < 2; ++half) {
            uint32_t a[4][4], b[4][4];
            #pragma unroll
            for (int mb = 0; mb < 4; ++mb)
                ldsm4(a[mb][0], a[mb][1], a[mb][2], a[mb][3],
                      Ab + swz64((aRow + mb * 16) * 64 + half * 32 + aHi));
            #pragma unroll
            for (int nbb = 0; nbb < 4; ++nbb)
                ldsm4(b[nbb][0], b[nbb][1], b[nbb][2], b[nbb][3],
                      Bb + swz64((bRow + nbb * 16) * 64 + half * 32 + bHi));
            #pragma unroll
            for (int mb = 0; mb < 4; ++mb)
                #pragma unroll
                for (int nbb = 0; nbb < 4; ++nbb) {
                    mma16816(acc[mb][2 * nbb],     a[mb], b[nbb][0], b[nbb][1]);
                    mma16816(acc[mb][2 * nbb + 1], a[mb], b[nbb][2], b[nbb][3]);
                }
        }
        __syncthreads();
    }

    // epilogue: bf16 score store + per-(row, tile) max + global hi-max
    float* red = (float*)smraw;                        // [128][2]
    #pragma unroll
    for (int mb = 0; mb < 4; ++mb) {
        #pragma unroll
        for (int half = 0; half < 2; ++half) {
            int row_l = warp_m * 64 + mb * 16 + half * 8 + (lane >> 2);
            int row = m0 + row_l;
            float bs = -3.0e38f;
            #pragma unroll
            for (int nb = 0; nb < 8; ++nb) {
                float2 s = make_float2(acc[mb][nb][half * 2],
                                       acc[mb][nb][half * 2 + 1]);
                __nv_bfloat162 h = __float22bfloat162_rn(s);
                *(__nv_bfloat162*)&g_s16[(size_t)row * V_SZ + n0 + warp_n * 64 +
                                         nb * 8 + (lane & 3) * 2] = h;
                bs = fmaxf(bs, fmaxf(__bfloat162float(h.x), __bfloat162float(h.y)));
            }
            #pragma unroll
            for (int o = 1; o <= 2; o <<= 1)
                bs = fmaxf(bs, __shfl_xor_sync(0xffffffffu, bs, o));
            if ((lane & 3) == 0) red[row_l * 2 + warp_n] = bs;
        }
    }
    __syncthreads();
    if (tid < 128) {
        float tm = fmaxf(red[tid * 2], red[tid * 2 + 1]);
        g_tilemax[(size_t)(m0 + tid) * NTILE + blockIdx.y] = tm;
        atomicMax(&g_hikey[m0 + tid], fkey(tm));
    }
}

// ---------------- K4: pass2 — prune tiles -> candidates -> exact + gather -------
__global__ __launch_bounds__(128) void k_pass2(const float* __restrict__ emb,
                                               float* __restrict__ out) {
    int m = blockIdx.x;
    int tid = threadIdx.x, wid = tid >> 5, lane = tid & 31;
    __shared__ int s_tcnt, s_ccnt;
    __shared__ short s_tiles[NTILE];
    __shared__ int s_cand[256];
    if (tid == 0) { s_tcnt = 0; s_ccnt = 0; }
    __syncthreads();

    float thr = unfkey(g_hikey[m]) - 0.013f * sqrtf(g_msq[m]);
    const float4* kr = (const float4*)(g_kw + (size_t)m * T_DIM);

    // phase 1: passing tiles (expected ~2 of 386)
    for (int t = tid; t < NTILE; t += 128)
        if (g_tilemax[(size_t)m * NTILE + t] >= thr) {
            int s = atomicAdd(&s_tcnt, 1);
            s_tiles[s] = (short)t;
        }
    __syncthreads();

    // phase 2: per-v candidates within passing tiles
    int ntl = s_tcnt;
    for (int i = 0; i < ntl; ++i) {
        int v = (int)s_tiles[i] * 128 + tid;
        float sv = __bfloat162float(g_s16[(size_t)m * V_SZ + v]);
        if (sv >= thr) {
            int s = atomicAdd(&s_ccnt, 1);
            if (s < 256) s_cand[s] = v;
            else {                                     // overflow fallback (rare)
                const float4* er = (const float4*)(emb + (size_t)v * T_DIM);
                float d = 0.f;
                for (int q = 0; q < 128; ++q) {
                    float4 a = kr[q], bb = er[q];
                    d = fmaf(a.x, bb.x, d); d = fmaf(a.y, bb.y, d);
                    d = fmaf(a.z, bb.z, d); d = fmaf(a.w, bb.w, d);
                }
                float ex = d * g_invn[v];
                unsigned long long pk = ((unsigned long long)fkey(ex) << 32) |
                                        (0xFFFFFFFFu - (unsigned)v);
                atomicMax(&g_best[m], pk);
            }
        }
    }
    __syncthreads();

    // phase 3: exact fp32 rescore, one warp per candidate
    int nc = min(s_ccnt, 256);
    for (int c = wid; c < nc; c += 4) {
        int v = s_cand[c];
        const float4* er = (const float4*)(emb + (size_t)v * T_DIM);
        float d = warp_dot(kr, er, lane);
        if (lane == 0) {
            float ex = d * g_invn[v];
            unsigned long long pk = ((unsigned long long)fkey(ex) << 32) |
                                    (0xFFFFFFFFu - (unsigned)v);
            atomicMax(&g_best[m], pk);
        }
    }
    __syncthreads();

    // phase 4: gather winner row (g_best[m] final: all its updates were ours)
    unsigned v = 0xFFFFFFFFu - (unsigned)(g_best[m] & 0xFFFFFFFFull);
    ((float4*)(out + (size_t)m * T_DIM))[tid] =
        ((const float4*)(emb + (size_t)v * T_DIM))[tid];
}

// ---------------- launcher --------------------------------------------------------
extern "C" void kernel_launch(void* const* d_in, const int* in_sizes, int n_in,
                              void* d_out, int out_size) {
    const float* audio = (const float*)d_in[0];
    const float* W     = (const float*)d_in[1];
    const float* b     = (const float*)d_in[2];
    const float* emb   = (const float*)d_in[3];
    float* out         = (float*)d_out;

    cudaFuncSetAttribute(k_pass1, cudaFuncAttributeMaxDynamicSharedMemorySize, DSMEM);

    k_init<<<2, 256>>>();
    dim3 g1(T_DIM / 64, M_KW / 64);
    k_proj<<<g1, 256>>>(audio, W, b);
    k_prepB<<<V_SZ / 8, 256>>>(emb);
    dim3 g3(M_KW / BM, V_SZ / BN);       // (4, 386)
    k_pass1<<<g3, 128, DSMEM>>>();
    k_pass2<<<M_KW, 128>>>(emb, out);
}

// round 6
// speedup vs baseline: 3.7902x; 1.0773x over previous
#include <cuda_runtime.h>
#include <cuda_bf16.h>
#include <cstdint>

#define M_KW 512
#define K_D  768
#define T_DIM 512
#define V_SZ 49408
#define NTILE (V_SZ / 128)         // 386
#define EPSF 1e-8f

// pass-1 GEMM tiling
#define BM 128
#define BN 128
#define BK 32
#define NKT (T_DIM / BK)           // 16
#define NSTAGE 4
#define A_STG (BM * 64)
#define B_STG (BN * 64)
#define STG_BYTES (A_STG + B_STG)  // 16384
#define DSMEM (NSTAGE * STG_BYTES + 1024)

// ---------------- device scratch ------------------------------------------------
__device__ float g_kw[M_KW * T_DIM];                       // fp32 projected keywords
__device__ __nv_bfloat16 g_A16[M_KW * T_DIM];              // bf16 of g_kw
__device__ __nv_bfloat16 g_B16[(size_t)V_SZ * T_DIM];      // bf16 normalized emb
__device__ float g_invn[V_SZ];                             // 1/max(||emb_v||,eps)
__device__ __nv_bfloat16 g_s16[(size_t)M_KW * V_SZ];       // bf16 scores (50 MB)
__device__ float g_tilemax[(size_t)M_KW * NTILE];          // per-row per-tile max
__device__ unsigned g_hikey[M_KW];                         // fkey(max bf16 score)
__device__ unsigned long long g_best[M_KW];                // packed exact argmax

// ---------------- helpers -------------------------------------------------------
__device__ __forceinline__ uint32_t sptr(const void* p) {
    return (uint32_t)__cvta_generic_to_shared(p);
}
__device__ __forceinline__ unsigned fkey(float s) {
    unsigned u = __float_as_uint(s);
    return (u & 0x80000000u) ? ~u : (u | 0x80000000u);
}
__device__ __forceinline__ float unfkey(unsigned k) {
    return (k & 0x80000000u) ? __uint_as_float(k ^ 0x80000000u) : __uint_as_float(~k);
}
__device__ __forceinline__ uint32_t swz64(uint32_t off) {
    return off ^ ((off >> 3) & 0x30);
}
__device__ __forceinline__ void cpa16(uint32_t dst, const void* src) {
    asm volatile("cp.async.cg.shared.global [%0], [%1], 16;" :: "r"(dst), "l"(src));
}
__device__ __forceinline__ void ldsm4(uint32_t& r0, uint32_t& r1, uint32_t& r2,
                                      uint32_t& r3, uint32_t addr) {
    asm volatile("ldmatrix.sync.aligned.m8n8.x4.shared.b16 {%0,%1,%2,%3}, [%4];"
                 : "=r"(r0), "=r"(r1), "=r"(r2), "=r"(r3) : "r"(addr));
}
__device__ __forceinline__ void mma16816(float* c, const uint32_t* a,
                                         uint32_t b0, uint32_t b1) {
    asm volatile(
        "mma.sync.aligned.m16n8k16.row.col.f32.bf16.bf16.f32 "
        "{%0,%1,%2,%3}, {%4,%5,%6,%7}, {%8,%9}, {%0,%1,%2,%3};"
        : "+f"(c[0]), "+f"(c[1]), "+f"(c[2]), "+f"(c[3])
        : "r"(a[0]), "r"(a[1]), "r"(a[2]), "r"(a[3]), "r"(b0), "r"(b1));
}
__device__ __forceinline__ float warp_dot(const float4* kr, const float4* er, int lane) {
    float d0 = 0.f, d1 = 0.f;
    #pragma unroll
    for (int i = 0; i < 4; i += 2) {
        float4 a0 = kr[lane + i * 32],       b0 = er[lane + i * 32];
        float4 a1 = kr[lane + (i + 1) * 32], b1 = er[lane + (i + 1) * 32];
        d0 = fmaf(a0.x, b0.x, d0); d0 = fmaf(a0.y, b0.y, d0);
        d0 = fmaf(a0.z, b0.z, d0); d0 = fmaf(a0.w, b0.w, d0);
        d1 = fmaf(a1.x, b1.x, d1); d1 = fmaf(a1.y, b1.y, d1);
        d1 = fmaf(a1.z, b1.z, d1); d1 = fmaf(a1.w, b1.w, d1);
    }
    float d = d0 + d1;
    #pragma unroll
    for (int o = 16; o; o >>= 1) d += __shfl_xor_sync(0xffffffffu, d, o);
    return d;
}

// ---------------- K1: fused prep -------------------------------------------------
// blocks [0,64): proj 512x512 = audio@W + b -> g_kw fp32 + g_A16 bf16
// blocks [64, 64+6176): normalize emb rows -> g_B16 bf16 + g_invn
// block 0 additionally zeroes g_hikey.
__global__ __launch_bounds__(256) void k_prep(const float* __restrict__ A,
                                              const float* __restrict__ W,
                                              const float* __restrict__ bias,
                                              const float* __restrict__ emb) {
    __shared__ float As[16][68];
    __shared__ float Ws[16][64];
    int tid = threadIdx.x;

    if (blockIdx.x < 64) {
        if (blockIdx.x == 0) { g_hikey[tid] = 0u; g_hikey[tid + 256] = 0u; }
        const int TBK = 16;
        int tx = tid & 15, ty = tid >> 4;
        int n0 = (blockIdx.x & 7) * 64, m0 = (blockIdx.x >> 3) * 64;
        float acc[4][4] = {};
        for (int k0 = 0; k0 < K_D; k0 += TBK) {
            #pragma unroll
            for (int i = 0; i < 4; ++i) {
                int idx = tid + i * 256;
                int r = idx >> 4, kk = idx & 15;
                As[kk][r] = A[(m0 + r) * K_D + k0 + kk];
            }
            #pragma unroll
            for (int i = 0; i < 4; ++i) {
                int idx = tid + i * 256;
                int kk = idx >> 6, n = idx & 63;
                Ws[kk][n] = W[(k0 + kk) * T_DIM + n0 + n];
            }
            __syncthreads();
            #pragma unroll
            for (int kk = 0; kk < TBK; ++kk) {
                float av[4], bv[4];
                #pragma unroll
                for (int i = 0; i < 4; ++i) av[i] = As[kk][ty * 4 + i];
                #pragma unroll
                for (int j = 0; j < 4; ++j) bv[j] = Ws[kk][tx * 4 + j];
                #pragma unroll
                for (int i = 0; i < 4; ++i)
                    #pragma unroll
                    for (int j = 0; j < 4; ++j)
                        acc[i][j] = fmaf(av[i], bv[j], acc[i][j]);
            }
            __syncthreads();
        }
        #pragma unroll
        for (int i = 0; i < 4; ++i) {
            int m = m0 + ty * 4 + i;
            int n = n0 + tx * 4;
            float x[4];
            __nv_bfloat16 hi[4];
            #pragma unroll
            for (int j = 0; j < 4; ++j) {
                x[j] = acc[i][j] + bias[n + j];
                hi[j] = __float2bfloat16(x[j]);
            }
            *(float4*)&g_kw[(size_t)m * T_DIM + n] = *(float4*)x;
            *(uint2*)&g_A16[(size_t)m * T_DIM + n] = *(uint2*)hi;
        }
    } else {
        int v = (blockIdx.x - 64) * 8 + (tid >> 5);
        int lane = tid & 31;
        const float4* p = (const float4*)(emb + (size_t)v * T_DIM);
        float4 vals[4];
        float ss = 0.f;
        #pragma unroll
        for (int i = 0; i < 4; ++i) {
            vals[i] = p[lane + i * 32];
            ss += vals[i].x * vals[i].x + vals[i].y * vals[i].y
                + vals[i].z * vals[i].z + vals[i].w * vals[i].w;
        }
        #pragma unroll
        for (int o = 16; o; o >>= 1) ss += __shfl_xor_sync(0xffffffffu, ss, o);
        float inv = 1.0f / fmaxf(sqrtf(ss), EPSF);
        if (lane == 0) g_invn[v] = inv;
        #pragma unroll
        for (int i = 0; i < 4; ++i) {
            __nv_bfloat16 hi[4];
            hi[0] = __float2bfloat16(vals[i].x * inv);
            hi[1] = __float2bfloat16(vals[i].y * inv);
            hi[2] = __float2bfloat16(vals[i].z * inv);
            hi[3] = __float2bfloat16(vals[i].w * inv);
            int idx = (lane + i * 32) * 4;
            *(uint2*)&g_B16[(size_t)v * T_DIM + idx] = *(uint2*)hi;
        }
    }
}

// ---------------- K2: pass1 — bf16 GEMM, bf16 scores + tile maxima --------------
__device__ __forceinline__ void fill_stage(uint32_t stg, int m0, int n0, int kt, int tid) {
    int kk = kt * 32;
    #pragma unroll
    for (int i = 0; i < 4; ++i) {
        int c = tid + i * 128;
        int r = c >> 2, cc = c & 3;
        cpa16(stg + swz64(r * 64 + cc * 16),
              &g_A16[(size_t)(m0 + r) * T_DIM + kk + cc * 8]);
    }
    #pragma unroll
    for (int i = 0; i < 4; ++i) {
        int c = tid + i * 128;
        int r = c >> 2, cc = c & 3;
        cpa16(stg + A_STG + swz64(r * 64 + cc * 16),
              &g_B16[(size_t)(n0 + r) * T_DIM + kk + cc * 8]);
    }
    asm volatile("cp.async.commit_group;" ::: "memory");
}

__global__ __launch_bounds__(128, 2) void k_pass1() {
    extern __shared__ __align__(16) char smraw[];
    uint32_t sm0 = (sptr(smraw) + 1023) & ~1023u;
    int tid = threadIdx.x;
    int lane = tid & 31, wid = tid >> 5;
    int warp_m = wid & 1, warp_n = wid >> 1;
    int m0 = blockIdx.x * BM;
    int n0 = blockIdx.y * BN;

    float acc[4][8][4];
    #pragma unroll
    for (int i = 0; i < 4; ++i)
        #pragma unroll
        for (int j = 0; j < 8; ++j)
            #pragma unroll
            for (int k = 0; k < 4; ++k) acc[i][j][k] = 0.f;

    #pragma unroll
    for (int p = 0; p < NSTAGE - 1; ++p)
        fill_stage(sm0 + p * STG_BYTES, m0, n0, p, tid);

    int aRow = warp_m * 64 + (lane & 15);
    int aHi  = ((lane >> 4) & 1) * 16;
    int bRow = warp_n * 64 + ((lane >> 4) & 1) * 8 + (lane & 7);
    int bHi  = ((lane >> 3) & 1) * 16;

    for (int kt = 0; kt < NKT; ++kt) {
        asm volatile("cp.async.wait_group 2;" ::: "memory");
        __syncthreads();                      // single barrier/iter: RAW + WAR
        int fk = kt + NSTAGE - 1;
        if (fk < NKT)
            fill_stage(sm0 + (fk & 3) * STG_BYTES, m0, n0, fk, tid);

        uint32_t Ab = sm0 + (kt & 3) * STG_BYTES;
        uint32_t Bb = Ab + A_STG;
        uint32_t a[2][4][4], b[2][4][4];
        #pragma unroll
        for (int half = 0; half < 2; ++half) {   // batch ALL ldsm first
            #pragma unroll
            for (int mb = 0; mb < 4; ++mb)
                ldsm4(a[half][mb][0], a[half][mb][1], a[half][mb][2], a[half][mb][3],
                      Ab + swz64((aRow + mb * 16) * 64 + half * 32 + aHi));
            #pragma unroll
            for (int nbb = 0; nbb < 4; ++nbb)
                ldsm4(b[half][nbb][0], b[half][nbb][1], b[half][nbb][2], b[half][nbb][3],
                      Bb + swz64((bRow + nbb * 16) * 64 + half * 32 + bHi));
        }
        #pragma unroll
        for (int half = 0; half < 2; ++half)
            #pragma unroll
            for (int mb = 0; mb < 4; ++mb)
                #pragma unroll
                for (int nbb = 0; nbb < 4; ++nbb) {
                    mma16816(acc[mb][2 * nbb],     a[half][mb], b[half][nbb][0], b[half][nbb][1]);
                    mma16816(acc[mb][2 * nbb + 1], a[half][mb], b[half][nbb][2], b[half][nbb][3]);
                }
    }
    __syncthreads();                           // protect smem reuse by epilogue

    // epilogue: bf16 score store + per-(row, tile) max + global hi-max
    float* red = (float*)smraw;                // [128][2]
    #pragma unroll
    for (int mb = 0; mb < 4; ++mb) {
        #pragma unroll
        for (int half = 0; half < 2; ++half) {
            int row_l = warp_m * 64 + mb * 16 + half * 8 + (lane >> 2);
            int row = m0 + row_l;
            float bs = -3.0e38f;
            #pragma unroll
            for (int nb = 0; nb < 8; ++nb) {
                float2 s = make_float2(acc[mb][nb][half * 2],
                                       acc[mb][nb][half * 2 + 1]);
                __nv_bfloat162 h = __float22bfloat162_rn(s);
                *(__nv_bfloat162*)&g_s16[(size_t)row * V_SZ + n0 + warp_n * 64 +
                                         nb * 8 + (lane & 3) * 2] = h;
                bs = fmaxf(bs, fmaxf(__bfloat162float(h.x), __bfloat162float(h.y)));
            }
            #pragma unroll
            for (int o = 1; o <= 2; o <<= 1)
                bs = fmaxf(bs, __shfl_xor_sync(0xffffffffu, bs, o));
            if ((lane & 3) == 0) red[row_l * 2 + warp_n] = bs;
        }
    }
    __syncthreads();
    if (tid < 128) {
        float tm = fmaxf(red[tid * 2], red[tid * 2 + 1]);
        g_tilemax[(size_t)(m0 + tid) * NTILE + blockIdx.y] = tm;
        atomicMax(&g_hikey[m0 + tid], fkey(tm));
    }
}

// ---------------- K3: pass2 — prune -> exact rescore -> gather ------------------
__global__ __launch_bounds__(128) void k_pass2(const float* __restrict__ emb,
                                               float* __restrict__ out) {
    int m = blockIdx.x;
    int tid = threadIdx.x, wid = tid >> 5, lane = tid & 31;
    __shared__ int s_tcnt, s_ccnt;
    __shared__ float s_thr;
    __shared__ float s_red[4];
    __shared__ short s_tiles[NTILE];
    __shared__ int s_cand[256];
    const float4* kr = (const float4*)(g_kw + (size_t)m * T_DIM);

    // phase 0: ||kw_m||^2, threshold, init
    {
        float4 a = kr[tid];
        float ss = a.x * a.x + a.y * a.y + a.z * a.z + a.w * a.w;
        #pragma unroll
        for (int o = 16; o; o >>= 1) ss += __shfl_xor_sync(0xffffffffu, ss, o);
        if (lane == 0) s_red[wid] = ss;
        if (tid == 0) { s_tcnt = 0; s_ccnt = 0; g_best[m] = 0ull; }
    }
    __syncthreads();
    if (tid == 0) {
        float nrm = sqrtf(s_red[0] + s_red[1] + s_red[2] + s_red[3]);
        s_thr = unfkey(g_hikey[m]) - 0.013f * nrm;
    }
    __syncthreads();
    float thr = s_thr;

    // phase 1: passing tiles (expected ~2 of 386)
    for (int t = tid; t < NTILE; t += 128)
        if (g_tilemax[(size_t)m * NTILE + t] >= thr) {
            int s = atomicAdd(&s_tcnt, 1);
            s_tiles[s] = (short)t;
        }
    __syncthreads();

    // phase 2: per-v candidates within passing tiles
    int ntl = s_tcnt;
    for (int i = 0; i < ntl; ++i) {
        int v = (int)s_tiles[i] * 128 + tid;
        float sv = __bfloat162float(g_s16[(size_t)m * V_SZ + v]);
        if (sv >= thr) {
            int s = atomicAdd(&s_ccnt, 1);
            if (s < 256) s_cand[s] = v;
            else {                                     // overflow fallback (rare)
                const float4* er = (const float4*)(emb + (size_t)v * T_DIM);
                float d = 0.f;
                for (int q = 0; q < 128; ++q) {
                    float4 a = kr[q], bb = er[q];
                    d = fmaf(a.x, bb.x, d); d = fmaf(a.y, bb.y, d);
                    d = fmaf(a.z, bb.z, d); d = fmaf(a.w, bb.w, d);
                }
                float ex = d * g_invn[v];
                unsigned long long pk = ((unsigned long long)fkey(ex) << 32) |
                                        (0xFFFFFFFFu - (unsigned)v);
                atomicMax(&g_best[m], pk);
            }
        }
    }
    __syncthreads();

    // phase 3: exact fp32 rescore, one warp per candidate
    int nc = min(s_ccnt, 256);
    for (int c = wid; c < nc; c += 4) {
        int v = s_cand[c];
        const float4* er = (const float4*)(emb + (size_t)v * T_DIM);
        float d = warp_dot(kr, er, lane);
        if (lane == 0) {
            float ex = d * g_invn[v];
            unsigned long long pk = ((unsigned long long)fkey(ex) << 32) |
                                    (0xFFFFFFFFu - (unsigned)v);
            atomicMax(&g_best[m], pk);
        }
    }
    __syncthreads();

    // phase 4: gather winner row
    unsigned v = 0xFFFFFFFFu - (unsigned)(g_best[m] & 0xFFFFFFFFull);
    ((float4*)(out + (size_t)m * T_DIM))[tid] =
        ((const float4*)(emb + (size_t)v * T_DIM))[tid];
}

// ---------------- launcher --------------------------------------------------------
extern "C" void kernel_launch(void* const* d_in, const int* in_sizes, int n_in,
                              void* d_out, int out_size) {
    const float* audio = (const float*)d_in[0];
    const float* W     = (const float*)d_in[1];
    const float* b     = (const float*)d_in[2];
    const float* emb   = (const float*)d_in[3];
    float* out         = (float*)d_out;

    cudaFuncSetAttribute(k_pass1, cudaFuncAttributeMaxDynamicSharedMemorySize, DSMEM);

    k_prep<<<64 + V_SZ / 8, 256>>>(audio, W, b, emb);
    dim3 g3(M_KW / BM, V_SZ / BN);       // (4, 386)
    k_pass1<<<g3, 128, DSMEM>>>();
    k_pass2<<<M_KW, 128>>>(emb, out);
}